// round 1
// baseline (speedup 1.0000x reference)
#include <cuda_runtime.h>
#include <math.h>

#define NV  100000
#define EE  1600000
#define ET  1700000      // EE + NV self-loops
#define FIN 512
#define D1  64           // H1*C1
#define H1N 8
#define D2  16

// ---- scratch (device globals; no allocations allowed) ----
__device__ float g_hp1[(size_t)NV * D1];          // x @ W1           [N,64]
__device__ float g_al1s[NV * H1N];                // src logits       [N,8]
__device__ float g_al1d[NV * H1N];                // dst logits       [N,8]
__device__ float g_ee[(size_t)ET * H1N];          // edge weights     (reused layer2)
__device__ float g_den1[NV * H1N];                // softmax denom    [N,8]
__device__ float g_h1[(size_t)NV * D1];           // layer1 out / elu [N,64]
__device__ float g_hp2[(size_t)NV * D2];          // h1 @ W2          [N,16]
__device__ float g_al2s[NV];
__device__ float g_al2d[NV];
__device__ float g_den2[NV];

// ---------------- zero accumulators + output ----------------
__global__ void kzero_all(float* __restrict__ out) {
    int t = blockIdx.x * blockDim.x + threadIdx.x;
    if (t < NV * D1)  g_h1[t] = 0.f;
    if (t < NV * H1N) g_den1[t] = 0.f;
    if (t < NV)       g_den2[t] = 0.f;
    if (t < NV * D2)  out[t] = 0.f;
}

// ---------------- GEMM1: hp1 = x @ W1  (N x 512 x 64) ----------------
// 128-row tile, full 64 cols, BK=32, 128 threads, 8x8 micro-tile.
__global__ __launch_bounds__(128) void kgemm1(const float* __restrict__ x,
                                              const float* __restrict__ W) {
    __shared__ float As[128][33];   // [row][k], +1 pad: conflict-free
    __shared__ float Bs[32][64];    // [k][col]

    const int tid  = threadIdx.x;
    const int row0 = blockIdx.x * 128;
    const int tr   = (tid >> 3) * 8;   // 0..120
    const int tc   = (tid & 7) * 8;    // 0..56

    float acc[8][8];
#pragma unroll
    for (int i = 0; i < 8; i++)
#pragma unroll
        for (int j = 0; j < 8; j++) acc[i][j] = 0.f;

    for (int kk = 0; kk < FIN; kk += 32) {
        // load x tile: 128x32 floats = 1024 float4; 8 per thread
#pragma unroll
        for (int l = 0; l < 8; l++) {
            int f  = l * 128 + tid;
            int r  = f >> 3;
            int c4 = (f & 7) << 2;
            int row = row0 + r;
            float4 v;
            if (row < NV) v = *(const float4*)(x + (size_t)row * FIN + kk + c4);
            else          v = make_float4(0.f, 0.f, 0.f, 0.f);
            As[r][c4 + 0] = v.x; As[r][c4 + 1] = v.y;
            As[r][c4 + 2] = v.z; As[r][c4 + 3] = v.w;
        }
        // load W tile: 32x64 floats = 512 float4; 4 per thread
#pragma unroll
        for (int l = 0; l < 4; l++) {
            int f  = l * 128 + tid;
            int r  = f >> 4;
            int c4 = (f & 15) << 2;
            *(float4*)&Bs[r][c4] = *(const float4*)(W + (size_t)(kk + r) * D1 + c4);
        }
        __syncthreads();

#pragma unroll
        for (int k = 0; k < 32; k++) {
            float a[8], b[8];
#pragma unroll
            for (int i = 0; i < 8; i++) a[i] = As[tr + i][k];
            float4 b0 = *(float4*)&Bs[k][tc];
            float4 b1 = *(float4*)&Bs[k][tc + 4];
            b[0] = b0.x; b[1] = b0.y; b[2] = b0.z; b[3] = b0.w;
            b[4] = b1.x; b[5] = b1.y; b[6] = b1.z; b[7] = b1.w;
#pragma unroll
            for (int i = 0; i < 8; i++)
#pragma unroll
                for (int j = 0; j < 8; j++) acc[i][j] = fmaf(a[i], b[j], acc[i][j]);
        }
        __syncthreads();
    }

#pragma unroll
    for (int i = 0; i < 8; i++) {
        int row = row0 + tr + i;
        if (row < NV) {
            float4 s0 = make_float4(acc[i][0], acc[i][1], acc[i][2], acc[i][3]);
            float4 s1 = make_float4(acc[i][4], acc[i][5], acc[i][6], acc[i][7]);
            *(float4*)(g_hp1 + (size_t)row * D1 + tc)     = s0;
            *(float4*)(g_hp1 + (size_t)row * D1 + tc + 4) = s1;
        }
    }
}

// ---------------- attention logit projections, layer 1 ----------------
__global__ void kal1(const float* __restrict__ a1s, const float* __restrict__ a1d) {
    int t = blockIdx.x * blockDim.x + threadIdx.x;
    if (t >= NV * H1N) return;
    int n = t >> 3, h = t & 7;
    const float* hp = g_hp1 + (size_t)n * D1 + h * 8;
    float s = 0.f, d = 0.f;
#pragma unroll
    for (int c = 0; c < 8; c++) {
        float v = hp[c];
        s = fmaf(v, a1s[h * 8 + c], s);
        d = fmaf(v, a1d[h * 8 + c], d);
    }
    g_al1s[t] = s;
    g_al1d[t] = d;
}

__device__ __forceinline__ void edge_sd(int e, const int* __restrict__ src,
                                        const int* __restrict__ dst, int& s, int& d) {
    if (e < EE) { s = src[e]; d = dst[e]; }
    else        { s = e - EE; d = s; }
}

// ---------------- layer-1 edge pass A: w = exp(lrelu(..)), denom ----------------
__global__ void kedgeA1(const int* __restrict__ src, const int* __restrict__ dst) {
    int t = blockIdx.x * blockDim.x + threadIdx.x;
    if (t >= ET * H1N) return;
    int e = t >> 3, h = t & 7;
    int s, d; edge_sd(e, src, dst, s, d);
    float v = g_al1s[s * H1N + h] + g_al1d[d * H1N + h];
    v = (v > 0.f) ? v : 0.2f * v;       // leaky_relu
    float w = __expf(v);                // stable: logits are tiny, skip segment-max
    g_ee[t] = w;
    atomicAdd(&g_den1[d * H1N + h], w);
}

// ---------------- normalize edge weights -> alpha ----------------
__global__ void knorm1(const int* __restrict__ src, const int* __restrict__ dst) {
    int t = blockIdx.x * blockDim.x + threadIdx.x;
    if (t >= ET * H1N) return;
    int e = t >> 3, h = t & 7;
    int s, d; edge_sd(e, src, dst, s, d);
    g_ee[t] = g_ee[t] / g_den1[d * H1N + h];
}

// ---------------- layer-1 edge pass B: scatter hp[src]*alpha ----------------
__global__ void kedgeB1(const int* __restrict__ src, const int* __restrict__ dst) {
    long long t = (long long)blockIdx.x * blockDim.x + threadIdx.x;
    if (t >= (long long)ET * D1) return;
    int e   = (int)(t >> 6);
    int idx = (int)(t & 63);
    int h   = idx >> 3;
    int s, d; edge_sd(e, src, dst, s, d);
    float alpha = g_ee[(size_t)e * H1N + h];
    atomicAdd(&g_h1[(size_t)d * D1 + idx], g_hp1[(size_t)s * D1 + idx] * alpha);
}

// ---------------- bias + ELU ----------------
__global__ void kelu(const float* __restrict__ b1) {
    int t = blockIdx.x * blockDim.x + threadIdx.x;
    if (t >= NV * D1) return;
    float v = g_h1[t] + b1[t & 63];
    g_h1[t] = (v > 0.f) ? v : expm1f(v);
}

// ---------------- GEMM2: hp2 = h1 @ W2  (N x 64 x 16) ----------------
__global__ __launch_bounds__(256) void kgemm2(const float* __restrict__ W2) {
    __shared__ float Ws[64 * 16];
    __shared__ float Hs[64 * 64];
    int tid = threadIdx.x;
    int n0  = blockIdx.x * 64;
    for (int i = tid; i < 1024; i += 256) Ws[i] = W2[i];
    for (int i = tid; i < 4096; i += 256) {
        int n = n0 + (i >> 6);
        Hs[i] = (n < NV) ? g_h1[(size_t)n * D1 + (i & 63)] : 0.f;
    }
    __syncthreads();
#pragma unroll
    for (int o = tid; o < 1024; o += 256) {
        int n = o >> 4, c = o & 15;
        float acc = 0.f;
#pragma unroll
        for (int k = 0; k < 64; k++) acc = fmaf(Hs[n * 64 + k], Ws[k * 16 + c], acc);
        int node = n0 + n;
        if (node < NV) g_hp2[(size_t)node * D2 + c] = acc;
    }
}

// ---------------- attention logit projections, layer 2 ----------------
__global__ void kal2(const float* __restrict__ a2s, const float* __restrict__ a2d) {
    int n = blockIdx.x * blockDim.x + threadIdx.x;
    if (n >= NV) return;
    const float* hp = g_hp2 + (size_t)n * D2;
    float s = 0.f, d = 0.f;
#pragma unroll
    for (int c = 0; c < 16; c++) {
        float v = hp[c];
        s = fmaf(v, a2s[c], s);
        d = fmaf(v, a2d[c], d);
    }
    g_al2s[n] = s;
    g_al2d[n] = d;
}

// ---------------- layer-2 edge passes ----------------
__global__ void kedgeA2(const int* __restrict__ src, const int* __restrict__ dst) {
    int e = blockIdx.x * blockDim.x + threadIdx.x;
    if (e >= ET) return;
    int s, d; edge_sd(e, src, dst, s, d);
    float v = g_al2s[s] + g_al2d[d];
    v = (v > 0.f) ? v : 0.2f * v;
    float w = __expf(v);
    g_ee[e] = w;
    atomicAdd(&g_den2[d], w);
}

__global__ void knorm2(const int* __restrict__ src, const int* __restrict__ dst) {
    int e = blockIdx.x * blockDim.x + threadIdx.x;
    if (e >= ET) return;
    int s, d; edge_sd(e, src, dst, s, d);
    g_ee[e] = g_ee[e] / g_den2[d];
}

__global__ void kedgeB2(const int* __restrict__ src, const int* __restrict__ dst,
                        float* __restrict__ out) {
    long long t = (long long)blockIdx.x * blockDim.x + threadIdx.x;
    if (t >= (long long)ET * D2) return;
    int e = (int)(t >> 4);
    int c = (int)(t & 15);
    int s, d; edge_sd(e, src, dst, s, d);
    float alpha = g_ee[e];
    atomicAdd(&out[(size_t)d * D2 + c], g_hp2[(size_t)s * D2 + c] * alpha);
}

// ---------------- bias + log_softmax ----------------
__global__ void kfinal(const float* __restrict__ b2, float* __restrict__ out) {
    int n = blockIdx.x * blockDim.x + threadIdx.x;
    if (n >= NV) return;
    float v[16];
    float m = -INFINITY;
#pragma unroll
    for (int c = 0; c < 16; c++) {
        v[c] = out[(size_t)n * D2 + c] + b2[c];
        m = fmaxf(m, v[c]);
    }
    float sum = 0.f;
#pragma unroll
    for (int c = 0; c < 16; c++) sum += __expf(v[c] - m);
    float lse = m + logf(sum);
#pragma unroll
    for (int c = 0; c < 16; c++) out[(size_t)n * D2 + c] = v[c] - lse;
}

// ---------------- launch ----------------
extern "C" void kernel_launch(void* const* d_in, const int* in_sizes, int n_in,
                              void* d_out, int out_size) {
    const float* x   = (const float*)d_in[0];
    const int*   ei  = (const int*)d_in[1];
    const float* W1  = (const float*)d_in[2];
    const float* a1s = (const float*)d_in[3];
    const float* a1d = (const float*)d_in[4];
    const float* b1  = (const float*)d_in[5];
    const float* W2  = (const float*)d_in[6];
    const float* a2s = (const float*)d_in[7];
    const float* a2d = (const float*)d_in[8];
    const float* b2  = (const float*)d_in[9];
    float* out = (float*)d_out;

    const int* src = ei;        // edge_index[0]
    const int* dst = ei + EE;   // edge_index[1]

    kzero_all<<<(NV * D1 + 255) / 256, 256>>>(out);
    kgemm1<<<(NV + 127) / 128, 128>>>(x, W1);
    kal1<<<(NV * H1N + 255) / 256, 256>>>(a1s, a1d);
    kedgeA1<<<(ET * H1N + 255) / 256, 256>>>(src, dst);
    knorm1<<<(ET * H1N + 255) / 256, 256>>>(src, dst);
    {
        long long tot = (long long)ET * D1;
        kedgeB1<<<(unsigned)((tot + 255) / 256), 256>>>(src, dst);
    }
    kelu<<<(NV * D1 + 255) / 256, 256>>>(b1);
    kgemm2<<<(NV + 63) / 64, 256>>>(W2);
    kal2<<<(NV + 255) / 256, 256>>>(a2s, a2d);
    kedgeA2<<<(ET + 255) / 256, 256>>>(src, dst);
    knorm2<<<(ET + 255) / 256, 256>>>(src, dst);
    {
        long long tot = (long long)ET * D2;
        kedgeB2<<<(unsigned)((tot + 255) / 256), 256>>>(src, dst, out);
    }
    kfinal<<<(NV + 255) / 256, 256>>>(b2, out);
}

// round 3
// speedup vs baseline: 2.0362x; 2.0362x over previous
#include <cuda_runtime.h>
#include <math.h>

#define NV  100000
#define EE  1600000
#define FIN 512
#define D1  64
#define H1N 8
#define D2  16
#define SCAN_CH 1024
#define SCAN_NB ((NV + SCAN_CH - 1) / SCAN_CH)   // 98

// ---- scratch (device globals; no allocations allowed) ----
__device__ float g_hp1[(size_t)NV * D1];     // x @ W1            [N,64]
__device__ float g_al1s[NV * H1N];           // src logits        [N,8]
__device__ float g_al1d[NV * H1N];           // dst logits        [N,8]
__device__ float g_h1[(size_t)NV * D1];      // layer1 out (elu)  [N,64]
__device__ float g_hp2[(size_t)NV * D2];     // h1 @ W2           [N,16]
__device__ float g_al2s[NV];
__device__ float g_al2d[NV];
__device__ int   g_cnt[NV];                  // dst histogram
__device__ int   g_cnt2[NV];                 // fill cursors
__device__ int   g_off[NV + 1];              // CSR offsets (real edges only)
__device__ int   g_esrc[EE];                 // CSR: src node per slot
__device__ int   g_blk[SCAN_NB];
__device__ int   g_blkoff[SCAN_NB];

// ---------------- zero CSR counters ----------------
__global__ void kzero() {
    int t = blockIdx.x * blockDim.x + threadIdx.x;
    if (t < NV) { g_cnt[t] = 0; g_cnt2[t] = 0; }
}

// ---------------- CSR: histogram of dst ----------------
__global__ void khist(const int* __restrict__ dst) {
    int e = blockIdx.x * blockDim.x + threadIdx.x;
    if (e < EE) atomicAdd(&g_cnt[dst[e]], 1);
}

// ---------------- CSR: scan stage 1 (block sums) ----------------
__global__ __launch_bounds__(256) void kscan1() {
    __shared__ int wsum[8];
    int b = blockIdx.x, t = threadIdx.x;
    int base = b * SCAN_CH + t * 4;
    int s = 0;
#pragma unroll
    for (int l = 0; l < 4; l++) s += (base + l < NV) ? g_cnt[base + l] : 0;
#pragma unroll
    for (int off = 16; off >= 1; off >>= 1) s += __shfl_down_sync(0xffffffffu, s, off);
    if ((t & 31) == 0) wsum[t >> 5] = s;
    __syncthreads();
    if (t == 0) {
        int tot = 0;
#pragma unroll
        for (int w = 0; w < 8; w++) tot += wsum[w];
        g_blk[b] = tot;
    }
}

// ---------------- CSR: scan stage 2 (scan block sums) ----------------
__global__ __launch_bounds__(128) void kscan2() {
    __shared__ int sm[128];
    int t = threadIdx.x;
    int v = (t < SCAN_NB) ? g_blk[t] : 0;
    sm[t] = v;
    __syncthreads();
    for (int off = 1; off < 128; off <<= 1) {
        int y = (t >= off) ? sm[t - off] : 0;
        __syncthreads();
        sm[t] += y;
        __syncthreads();
    }
    if (t < SCAN_NB) g_blkoff[t] = sm[t] - v;   // exclusive
}

// ---------------- CSR: scan stage 3 (write offsets) ----------------
__global__ __launch_bounds__(256) void kscan3() {
    __shared__ int wsum[8];
    int b = blockIdx.x, t = threadIdx.x;
    int lane = t & 31, w = t >> 5;
    int base = b * SCAN_CH + t * 4;
    int v[4];
#pragma unroll
    for (int l = 0; l < 4; l++) v[l] = (base + l < NV) ? g_cnt[base + l] : 0;
    int s4 = v[0] + v[1] + v[2] + v[3];
    int x = s4;
#pragma unroll
    for (int off = 1; off < 32; off <<= 1) {
        int y = __shfl_up_sync(0xffffffffu, x, off);
        if (lane >= off) x += y;
    }
    if (lane == 31) wsum[w] = x;
    __syncthreads();
    if (t < 8) {
        int y = wsum[t];
#pragma unroll
        for (int off = 1; off < 8; off <<= 1) {
            int z = __shfl_up_sync(0x000000ffu, y, off);
            if (t >= off) y += z;
        }
        wsum[t] = y;   // inclusive over warps
    }
    __syncthreads();
    int run = g_blkoff[b] + (x - s4) + (w > 0 ? wsum[w - 1] : 0);
#pragma unroll
    for (int l = 0; l < 4; l++) {
        if (base + l < NV) g_off[base + l] = run;
        run += v[l];
    }
    if (b == 0 && t == 0) g_off[NV] = EE;
}

// ---------------- CSR: fill ----------------
__global__ void kfill(const int* __restrict__ src, const int* __restrict__ dst) {
    int e = blockIdx.x * blockDim.x + threadIdx.x;
    if (e >= EE) return;
    int d = dst[e];
    int p = g_off[d] + atomicAdd(&g_cnt2[d], 1);
    g_esrc[p] = src[e];
}

// ---------------- GEMM1: hp1 = x @ W1, fused al1s/al1d epilogue ----------------
__global__ __launch_bounds__(128) void kgemm1(const float* __restrict__ x,
                                              const float* __restrict__ W,
                                              const float* __restrict__ a1s,
                                              const float* __restrict__ a1d) {
    __shared__ float As[128][33];
    __shared__ float Bs[32][64];
    const int tid  = threadIdx.x;
    const int row0 = blockIdx.x * 128;
    const int tr   = (tid >> 3) * 8;
    const int tc   = (tid & 7) * 8;

    float4 rx[8], rw[4];
#pragma unroll
    for (int l = 0; l < 8; l++) {
        int f = l * 128 + tid, r = f >> 3, c4 = (f & 7) << 2, row = row0 + r;
        rx[l] = (row < NV) ? *(const float4*)(x + (size_t)row * FIN + c4)
                           : make_float4(0.f, 0.f, 0.f, 0.f);
    }
#pragma unroll
    for (int l = 0; l < 4; l++) {
        int f = l * 128 + tid, r = f >> 4, c4 = (f & 15) << 2;
        rw[l] = *(const float4*)(W + (size_t)r * D1 + c4);
    }

    float acc[8][8];
#pragma unroll
    for (int i = 0; i < 8; i++)
#pragma unroll
        for (int j = 0; j < 8; j++) acc[i][j] = 0.f;

    for (int kk = 0; kk < FIN; kk += 32) {
#pragma unroll
        for (int l = 0; l < 8; l++) {
            int f = l * 128 + tid, r = f >> 3, c4 = (f & 7) << 2;
            As[r][c4 + 0] = rx[l].x; As[r][c4 + 1] = rx[l].y;
            As[r][c4 + 2] = rx[l].z; As[r][c4 + 3] = rx[l].w;
        }
#pragma unroll
        for (int l = 0; l < 4; l++) {
            int f = l * 128 + tid, r = f >> 4, c4 = (f & 15) << 2;
            *(float4*)&Bs[r][c4] = rw[l];
        }
        __syncthreads();

        if (kk + 32 < FIN) {
            int kn = kk + 32;
#pragma unroll
            for (int l = 0; l < 8; l++) {
                int f = l * 128 + tid, r = f >> 3, c4 = (f & 7) << 2, row = row0 + r;
                rx[l] = (row < NV) ? *(const float4*)(x + (size_t)row * FIN + kn + c4)
                                   : make_float4(0.f, 0.f, 0.f, 0.f);
            }
#pragma unroll
            for (int l = 0; l < 4; l++) {
                int f = l * 128 + tid, r = f >> 4, c4 = (f & 15) << 2;
                rw[l] = *(const float4*)(W + (size_t)(kn + r) * D1 + c4);
            }
        }

#pragma unroll
        for (int k = 0; k < 32; k++) {
            float a[8], b[8];
#pragma unroll
            for (int i = 0; i < 8; i++) a[i] = As[tr + i][k];
            float4 b0 = *(float4*)&Bs[k][tc];
            float4 b1 = *(float4*)&Bs[k][tc + 4];
            b[0] = b0.x; b[1] = b0.y; b[2] = b0.z; b[3] = b0.w;
            b[4] = b1.x; b[5] = b1.y; b[6] = b1.z; b[7] = b1.w;
#pragma unroll
            for (int i = 0; i < 8; i++)
#pragma unroll
                for (int j = 0; j < 8; j++) acc[i][j] = fmaf(a[i], b[j], acc[i][j]);
        }
        __syncthreads();
    }

    const int h = tc >> 3;
    float as[8], ad[8];
#pragma unroll
    for (int j = 0; j < 8; j++) { as[j] = a1s[h * 8 + j]; ad[j] = a1d[h * 8 + j]; }

#pragma unroll
    for (int i = 0; i < 8; i++) {
        int row = row0 + tr + i;
        if (row < NV) {
            *(float4*)(g_hp1 + (size_t)row * D1 + tc)     =
                make_float4(acc[i][0], acc[i][1], acc[i][2], acc[i][3]);
            *(float4*)(g_hp1 + (size_t)row * D1 + tc + 4) =
                make_float4(acc[i][4], acc[i][5], acc[i][6], acc[i][7]);
            float s = 0.f, d = 0.f;
#pragma unroll
            for (int j = 0; j < 8; j++) {
                s = fmaf(acc[i][j], as[j], s);
                d = fmaf(acc[i][j], ad[j], d);
            }
            g_al1s[row * H1N + h] = s;
            g_al1d[row * H1N + h] = d;
        }
    }
}

// ---------------- layer-1 aggregation: one warp per dst node ----------------
// Single pass: acc = sum_e w_e * hp1[src_e], den = sum_e w_e; out = acc/den.
// Fuses softmax-normalization, bias and ELU. No atomics, no edge-weight array.
// All shfls warp-uniform.
__global__ __launch_bounds__(256) void kagg1(const float* __restrict__ b1) {
    int gw = (blockIdx.x * blockDim.x + threadIdx.x) >> 5;
    if (gw >= NV) return;
    const int d    = gw;
    const int lane = threadIdx.x & 31;
    const int h_lo = lane >> 3;        // head of channel c = lane      (0..3)
    const int h_hi = 4 + (lane >> 3);  // head of channel c = lane + 32 (4..7)

    float ald = (lane < 8) ? g_al1d[d * H1N + lane] : 0.f;
    float acc0 = 0.f, acc1 = 0.f, den = 0.f;

    // self-loop: s = d
    {
        int s = d;
        float w = 0.f;
        if (lane < 8) {
            float v = g_al1s[s * H1N + lane] + ald;
            v = (v > 0.f) ? v : 0.2f * v;
            w = __expf(v);
            den += w;
        }
        float w_lo = __shfl_sync(0xffffffffu, w, h_lo);
        float w_hi = __shfl_sync(0xffffffffu, w, h_hi);
        acc0 = fmaf(g_hp1[(size_t)s * D1 + lane],      w_lo, acc0);
        acc1 = fmaf(g_hp1[(size_t)s * D1 + 32 + lane], w_hi, acc1);
    }

    const int beg = g_off[d], end = g_off[d + 1];
    for (int j = beg; j < end; j += 32) {
        int idx = j + lane;
        int sv  = g_esrc[(idx < end) ? idx : (end - 1)];
        int m   = end - j; if (m > 32) m = 32;
        for (int k = 0; k < m; k++) {
            int s = __shfl_sync(0xffffffffu, sv, k);
            float w = 0.f;
            if (lane < 8) {
                float v = g_al1s[s * H1N + lane] + ald;
                v = (v > 0.f) ? v : 0.2f * v;
                w = __expf(v);
                den += w;
            }
            float w_lo = __shfl_sync(0xffffffffu, w, h_lo);
            float w_hi = __shfl_sync(0xffffffffu, w, h_hi);
            acc0 = fmaf(g_hp1[(size_t)s * D1 + lane],      w_lo, acc0);
            acc1 = fmaf(g_hp1[(size_t)s * D1 + 32 + lane], w_hi, acc1);
        }
    }

    float den_lo = __shfl_sync(0xffffffffu, den, h_lo);
    float den_hi = __shfl_sync(0xffffffffu, den, h_hi);
    float v0 = acc0 / den_lo + b1[lane];
    float v1 = acc1 / den_hi + b1[lane + 32];
    v0 = (v0 > 0.f) ? v0 : expm1f(v0);   // ELU
    v1 = (v1 > 0.f) ? v1 : expm1f(v1);
    g_h1[(size_t)d * D1 + lane]      = v0;
    g_h1[(size_t)d * D1 + 32 + lane] = v1;
}

// ---------------- GEMM2: hp2 = h1 @ W2  (N x 64 x 16) ----------------
__global__ __launch_bounds__(256) void kgemm2(const float* __restrict__ W2) {
    __shared__ float Ws[64 * 16];
    __shared__ float Hs[64 * 64];
    int tid = threadIdx.x;
    int n0  = blockIdx.x * 64;
    for (int i = tid; i < 1024; i += 256) Ws[i] = W2[i];
    for (int i = tid; i < 4096; i += 256) {
        int n = n0 + (i >> 6);
        Hs[i] = (n < NV) ? g_h1[(size_t)n * D1 + (i & 63)] : 0.f;
    }
    __syncthreads();
#pragma unroll
    for (int o = tid; o < 1024; o += 256) {
        int n = o >> 4, c = o & 15;
        float acc = 0.f;
#pragma unroll
        for (int k = 0; k < 64; k++) acc = fmaf(Hs[n * 64 + k], Ws[k * 16 + c], acc);
        int node = n0 + n;
        if (node < NV) g_hp2[(size_t)node * D2 + c] = acc;
    }
}

// ---------------- layer-2 attention projections ----------------
__global__ void kal2(const float* __restrict__ a2s, const float* __restrict__ a2d) {
    int n = blockIdx.x * blockDim.x + threadIdx.x;
    if (n >= NV) return;
    const float* hp = g_hp2 + (size_t)n * D2;
    float s = 0.f, d = 0.f;
#pragma unroll
    for (int c = 0; c < 16; c++) {
        float v = hp[c];
        s = fmaf(v, a2s[c], s);
        d = fmaf(v, a2d[c], d);
    }
    g_al2s[n] = s;
    g_al2d[n] = d;
}

// ---------------- layer-2 aggregation + bias + log_softmax ----------------
// One warp per dst. Two edges per iteration; ALL shfls executed by the full
// warp with warp-uniform operands; halves consume alternate edges.
__global__ __launch_bounds__(256) void kagg2(const float* __restrict__ b2,
                                             float* __restrict__ out) {
    int gw = (blockIdx.x * blockDim.x + threadIdx.x) >> 5;
    if (gw >= NV) return;
    const int d    = gw;
    const int lane = threadIdx.x & 31;
    const int half = lane >> 4;
    const int hl   = lane & 15;

    float al2dd = g_al2d[d];
    float acc = 0.f, den = 0.f;

    // self-loop handled by half 0 only (no shfl involved)
    if (half == 0) {
        float v = g_al2s[d] + al2dd;
        v = (v > 0.f) ? v : 0.2f * v;
        float w = __expf(v);
        den += w;
        acc = fmaf(g_hp2[(size_t)d * D2 + hl], w, acc);
    }

    const int beg = g_off[d], end = g_off[d + 1];
    for (int j = beg; j < end; j += 32) {
        int idx = j + lane;
        int sv  = g_esrc[(idx < end) ? idx : (end - 1)];
        int m   = end - j; if (m > 32) m = 32;
        for (int k = 0; k < m; k += 2) {
            // both shfls executed by ALL lanes with uniform source lane
            int s0 = __shfl_sync(0xffffffffu, sv, k);
            int s1 = __shfl_sync(0xffffffffu, sv, (k + 1 < m) ? (k + 1) : k);
            int s  = (half == 0) ? s0 : s1;
            bool valid = (half == 0) || (k + 1 < m);
            if (valid) {
                float v = g_al2s[s] + al2dd;
                v = (v > 0.f) ? v : 0.2f * v;
                float w = __expf(v);
                den += w;
                acc = fmaf(g_hp2[(size_t)s * D2 + hl], w, acc);
            }
        }
    }
    // combine halves (acc/den replicated across the 16 lanes of each half)
    acc += __shfl_xor_sync(0xffffffffu, acc, 16);
    den += __shfl_xor_sync(0xffffffffu, den, 16);

    float v = acc / den + b2[hl];
    // log_softmax across 16 channels (both halves hold identical values)
    float mx = v;
#pragma unroll
    for (int off = 8; off >= 1; off >>= 1)
        mx = fmaxf(mx, __shfl_xor_sync(0xffffffffu, mx, off));
    float se = __expf(v - mx);
#pragma unroll
    for (int off = 8; off >= 1; off >>= 1)
        se += __shfl_xor_sync(0xffffffffu, se, off);
    float r = v - (mx + logf(se));
    if (lane < 16) out[(size_t)d * D2 + hl] = r;
}

// ---------------- launch ----------------
extern "C" void kernel_launch(void* const* d_in, const int* in_sizes, int n_in,
                              void* d_out, int out_size) {
    const float* x   = (const float*)d_in[0];
    const int*   ei  = (const int*)d_in[1];
    const float* W1  = (const float*)d_in[2];
    const float* a1s = (const float*)d_in[3];
    const float* a1d = (const float*)d_in[4];
    const float* b1  = (const float*)d_in[5];
    const float* W2  = (const float*)d_in[6];
    const float* a2s = (const float*)d_in[7];
    const float* a2d = (const float*)d_in[8];
    const float* b2  = (const float*)d_in[9];
    float* out = (float*)d_out;

    const int* src = ei;
    const int* dst = ei + EE;

    kzero<<<(NV + 255) / 256, 256>>>();
    khist<<<(EE + 255) / 256, 256>>>(dst);
    kscan1<<<SCAN_NB, 256>>>();
    kscan2<<<1, 128>>>();
    kscan3<<<SCAN_NB, 256>>>();
    kfill<<<(EE + 255) / 256, 256>>>(src, dst);

    kgemm1<<<(NV + 127) / 128, 128>>>(x, W1, a1s, a1d);
    kagg1<<<(NV * 32 + 255) / 256, 256>>>(b1);
    kgemm2<<<(NV + 63) / 64, 256>>>(W2);
    kal2<<<(NV + 255) / 256, 256>>>(a2s, a2d);
    kagg2<<<(NV * 32 + 255) / 256, 256>>>(b2, out);
}

// round 4
// speedup vs baseline: 2.1793x; 1.0703x over previous
#include <cuda_runtime.h>
#include <math.h>

#define NV  100000
#define EE  1600000
#define FIN 512
#define D1  64
#define H1N 8
#define D2  16
#define SCAN_CH 1024
#define SCAN_NB ((NV + SCAN_CH - 1) / SCAN_CH)   // 98

typedef unsigned long long u64;

// ---- packed f32x2 helpers ----
__device__ __forceinline__ void ffma2(u64& d, u64 a, u64 b) {
    asm("fma.rn.f32x2 %0, %1, %2, %0;" : "+l"(d) : "l"(a), "l"(b));
}
__device__ __forceinline__ u64 pack2(float x, float y) {
    u64 r;
    asm("mov.b64 %0, {%1, %2};" : "=l"(r) : "f"(x), "f"(y));
    return r;
}
__device__ __forceinline__ void unpack2(u64 v, float& x, float& y) {
    asm("mov.b64 {%0, %1}, %2;" : "=f"(x), "=f"(y) : "l"(v));
}

// ---- scratch (device globals; no allocations allowed) ----
__device__ float g_hp1[(size_t)NV * D1];     // x @ W1            [N,64]
__device__ float g_al1s[NV * H1N];           // src logits        [N,8]
__device__ float g_al1d[NV * H1N];           // dst logits        [N,8]
__device__ float g_h1[(size_t)NV * D1];      // layer1 out (elu)  [N,64]
__device__ float g_hp2[(size_t)NV * D2];     // h1 @ W2           [N,16]
__device__ float g_al2s[NV];
__device__ float g_al2d[NV];
__device__ int   g_cnt[NV];                  // dst histogram
__device__ int   g_cnt2[NV];                 // fill cursors
__device__ int   g_off[NV + 1];              // CSR offsets (real edges only)
__device__ int   g_esrc[EE];                 // CSR: src node per slot
__device__ int   g_blk[SCAN_NB];
__device__ int   g_blkoff[SCAN_NB];

// ---------------- zero CSR counters ----------------
__global__ void kzero() {
    int t = blockIdx.x * blockDim.x + threadIdx.x;
    if (t < NV) { g_cnt[t] = 0; g_cnt2[t] = 0; }
}

// ---------------- CSR: histogram of dst ----------------
__global__ void khist(const int* __restrict__ dst) {
    int e = blockIdx.x * blockDim.x + threadIdx.x;
    if (e < EE) atomicAdd(&g_cnt[dst[e]], 1);
}

// ---------------- CSR: scan stage 1 (block sums) ----------------
__global__ __launch_bounds__(256) void kscan1() {
    __shared__ int wsum[8];
    int b = blockIdx.x, t = threadIdx.x;
    int base = b * SCAN_CH + t * 4;
    int s = 0;
#pragma unroll
    for (int l = 0; l < 4; l++) s += (base + l < NV) ? g_cnt[base + l] : 0;
#pragma unroll
    for (int off = 16; off >= 1; off >>= 1) s += __shfl_down_sync(0xffffffffu, s, off);
    if ((t & 31) == 0) wsum[t >> 5] = s;
    __syncthreads();
    if (t == 0) {
        int tot = 0;
#pragma unroll
        for (int w = 0; w < 8; w++) tot += wsum[w];
        g_blk[b] = tot;
    }
}

// ---------------- CSR: scan stage 2 (scan block sums) ----------------
__global__ __launch_bounds__(128) void kscan2() {
    __shared__ int sm[128];
    int t = threadIdx.x;
    int v = (t < SCAN_NB) ? g_blk[t] : 0;
    sm[t] = v;
    __syncthreads();
    for (int off = 1; off < 128; off <<= 1) {
        int y = (t >= off) ? sm[t - off] : 0;
        __syncthreads();
        sm[t] += y;
        __syncthreads();
    }
    if (t < SCAN_NB) g_blkoff[t] = sm[t] - v;   // exclusive
}

// ---------------- CSR: scan stage 3 (write offsets) ----------------
__global__ __launch_bounds__(256) void kscan3() {
    __shared__ int wsum[8];
    int b = blockIdx.x, t = threadIdx.x;
    int lane = t & 31, w = t >> 5;
    int base = b * SCAN_CH + t * 4;
    int v[4];
#pragma unroll
    for (int l = 0; l < 4; l++) v[l] = (base + l < NV) ? g_cnt[base + l] : 0;
    int s4 = v[0] + v[1] + v[2] + v[3];
    int x = s4;
#pragma unroll
    for (int off = 1; off < 32; off <<= 1) {
        int y = __shfl_up_sync(0xffffffffu, x, off);
        if (lane >= off) x += y;
    }
    if (lane == 31) wsum[w] = x;
    __syncthreads();
    if (t < 8) {
        int y = wsum[t];
#pragma unroll
        for (int off = 1; off < 8; off <<= 1) {
            int z = __shfl_up_sync(0x000000ffu, y, off);
            if (t >= off) y += z;
        }
        wsum[t] = y;   // inclusive over warps
    }
    __syncthreads();
    int run = g_blkoff[b] + (x - s4) + (w > 0 ? wsum[w - 1] : 0);
#pragma unroll
    for (int l = 0; l < 4; l++) {
        if (base + l < NV) g_off[base + l] = run;
        run += v[l];
    }
    if (b == 0 && t == 0) g_off[NV] = EE;
}

// ---------------- CSR: fill ----------------
__global__ void kfill(const int* __restrict__ src, const int* __restrict__ dst) {
    int e = blockIdx.x * blockDim.x + threadIdx.x;
    if (e >= EE) return;
    int d = dst[e];
    int p = g_off[d] + atomicAdd(&g_cnt2[d], 1);
    g_esrc[p] = src[e];
}

// ---------------- GEMM1: hp1 = x @ W1 (f32x2), fused al1 epilogue ----------------
__global__ __launch_bounds__(128) void kgemm1(const float* __restrict__ x,
                                              const float* __restrict__ W,
                                              const float* __restrict__ a1s,
                                              const float* __restrict__ a1d) {
    __shared__ float As[128][33];
    __shared__ float Bs[32][64];
    const int tid  = threadIdx.x;
    const int row0 = blockIdx.x * 128;
    const int tr   = (tid >> 3) * 8;
    const int tc   = (tid & 7) * 8;

    float4 rx[8], rw[4];
#pragma unroll
    for (int l = 0; l < 8; l++) {
        int f = l * 128 + tid, r = f >> 3, c4 = (f & 7) << 2, row = row0 + r;
        rx[l] = (row < NV) ? *(const float4*)(x + (size_t)row * FIN + c4)
                           : make_float4(0.f, 0.f, 0.f, 0.f);
    }
#pragma unroll
    for (int l = 0; l < 4; l++) {
        int f = l * 128 + tid, r = f >> 4, c4 = (f & 15) << 2;
        rw[l] = *(const float4*)(W + (size_t)r * D1 + c4);
    }

    u64 acc2[8][4];
#pragma unroll
    for (int i = 0; i < 8; i++)
#pragma unroll
        for (int p = 0; p < 4; p++) acc2[i][p] = 0ULL;

    for (int kk = 0; kk < FIN; kk += 32) {
#pragma unroll
        for (int l = 0; l < 8; l++) {
            int f = l * 128 + tid, r = f >> 3, c4 = (f & 7) << 2;
            As[r][c4 + 0] = rx[l].x; As[r][c4 + 1] = rx[l].y;
            As[r][c4 + 2] = rx[l].z; As[r][c4 + 3] = rx[l].w;
        }
#pragma unroll
        for (int l = 0; l < 4; l++) {
            int f = l * 128 + tid, r = f >> 4, c4 = (f & 15) << 2;
            *(float4*)&Bs[r][c4] = rw[l];
        }
        __syncthreads();

        if (kk + 32 < FIN) {
            int kn = kk + 32;
#pragma unroll
            for (int l = 0; l < 8; l++) {
                int f = l * 128 + tid, r = f >> 3, c4 = (f & 7) << 2, row = row0 + r;
                rx[l] = (row < NV) ? *(const float4*)(x + (size_t)row * FIN + kn + c4)
                                   : make_float4(0.f, 0.f, 0.f, 0.f);
            }
#pragma unroll
            for (int l = 0; l < 4; l++) {
                int f = l * 128 + tid, r = f >> 4, c4 = (f & 15) << 2;
                rw[l] = *(const float4*)(W + (size_t)(kn + r) * D1 + c4);
            }
        }

#pragma unroll
        for (int k = 0; k < 32; k++) {
            u64 av[8], bv[4];
#pragma unroll
            for (int i = 0; i < 8; i++) {
                float a = As[tr + i][k];
                av[i] = pack2(a, a);
            }
            const u64* bp = (const u64*)&Bs[k][tc];   // 32B-aligned (tc mult of 8)
#pragma unroll
            for (int p = 0; p < 4; p++) bv[p] = bp[p];
#pragma unroll
            for (int i = 0; i < 8; i++)
#pragma unroll
                for (int p = 0; p < 4; p++) ffma2(acc2[i][p], av[i], bv[p]);
        }
        __syncthreads();
    }

    const int h = tc >> 3;
    float as[8], ad[8];
#pragma unroll
    for (int j = 0; j < 8; j++) { as[j] = a1s[h * 8 + j]; ad[j] = a1d[h * 8 + j]; }

#pragma unroll
    for (int i = 0; i < 8; i++) {
        int row = row0 + tr + i;
        if (row < NV) {
            float o[8];
#pragma unroll
            for (int p = 0; p < 4; p++) unpack2(acc2[i][p], o[2 * p], o[2 * p + 1]);
            *(float4*)(g_hp1 + (size_t)row * D1 + tc)     =
                make_float4(o[0], o[1], o[2], o[3]);
            *(float4*)(g_hp1 + (size_t)row * D1 + tc + 4) =
                make_float4(o[4], o[5], o[6], o[7]);
            float s = 0.f, d = 0.f;
#pragma unroll
            for (int j = 0; j < 8; j++) {
                s = fmaf(o[j], as[j], s);
                d = fmaf(o[j], ad[j], d);
            }
            g_al1s[row * H1N + h] = s;
            g_al1d[row * H1N + h] = d;
        }
    }
}

// ---------------- layer-1 aggregation: one warp per dst node ----------------
__global__ __launch_bounds__(256) void kagg1(const float* __restrict__ b1) {
    int gw = (blockIdx.x * blockDim.x + threadIdx.x) >> 5;
    if (gw >= NV) return;
    const int d    = gw;
    const int lane = threadIdx.x & 31;
    const int h_lo = lane >> 3;
    const int h_hi = 4 + (lane >> 3);

    float ald = (lane < 8) ? g_al1d[d * H1N + lane] : 0.f;
    float acc0 = 0.f, acc1 = 0.f, den = 0.f;

    // self-loop: s = d
    {
        int s = d;
        float w = 0.f;
        if (lane < 8) {
            float v = g_al1s[s * H1N + lane] + ald;
            v = (v > 0.f) ? v : 0.2f * v;
            w = __expf(v);
            den += w;
        }
        float w_lo = __shfl_sync(0xffffffffu, w, h_lo);
        float w_hi = __shfl_sync(0xffffffffu, w, h_hi);
        acc0 = fmaf(g_hp1[(size_t)s * D1 + lane],      w_lo, acc0);
        acc1 = fmaf(g_hp1[(size_t)s * D1 + 32 + lane], w_hi, acc1);
    }

    const int beg = g_off[d], end = g_off[d + 1];
    for (int j = beg; j < end; j += 32) {
        int idx = j + lane;
        int sv  = g_esrc[(idx < end) ? idx : (end - 1)];
        int m   = end - j; if (m > 32) m = 32;
        for (int k = 0; k < m; k++) {
            int s = __shfl_sync(0xffffffffu, sv, k);
            float w = 0.f;
            if (lane < 8) {
                float v = g_al1s[s * H1N + lane] + ald;
                v = (v > 0.f) ? v : 0.2f * v;
                w = __expf(v);
                den += w;
            }
            float w_lo = __shfl_sync(0xffffffffu, w, h_lo);
            float w_hi = __shfl_sync(0xffffffffu, w, h_hi);
            acc0 = fmaf(g_hp1[(size_t)s * D1 + lane],      w_lo, acc0);
            acc1 = fmaf(g_hp1[(size_t)s * D1 + 32 + lane], w_hi, acc1);
        }
    }

    float den_lo = __shfl_sync(0xffffffffu, den, h_lo);
    float den_hi = __shfl_sync(0xffffffffu, den, h_hi);
    float v0 = acc0 / den_lo + b1[lane];
    float v1 = acc1 / den_hi + b1[lane + 32];
    v0 = (v0 > 0.f) ? v0 : expm1f(v0);   // ELU
    v1 = (v1 > 0.f) ? v1 : expm1f(v1);
    g_h1[(size_t)d * D1 + lane]      = v0;
    g_h1[(size_t)d * D1 + 32 + lane] = v1;
}

// ---------------- GEMM2 (f32x2, one thread/node) + fused al2 ----------------
__global__ __launch_bounds__(256) void kgemm2(const float* __restrict__ W2,
                                              const float* __restrict__ a2s,
                                              const float* __restrict__ a2d) {
    __shared__ float Ws[D1 * D2];     // 64x16
    __shared__ float A2[2 * D2];
    int tid = threadIdx.x;
    for (int i = tid; i < D1 * D2; i += 256) Ws[i] = W2[i];
    if (tid < D2)           A2[tid] = a2s[tid];
    else if (tid < 2 * D2)  A2[tid] = a2d[tid - D2];
    __syncthreads();

    int n = blockIdx.x * 256 + tid;
    if (n >= NV) return;

    u64 acc[8];
#pragma unroll
    for (int p = 0; p < 8; p++) acc[p] = 0ULL;

    const float* hr = g_h1 + (size_t)n * D1;
#pragma unroll
    for (int k0 = 0; k0 < D1; k0 += 4) {
        float4 hv = *(const float4*)(hr + k0);
        float h4[4] = {hv.x, hv.y, hv.z, hv.w};
#pragma unroll
        for (int j = 0; j < 4; j++) {
            u64 a = pack2(h4[j], h4[j]);
            const u64* wp = (const u64*)&Ws[(k0 + j) * D2];  // broadcast LDS.64
#pragma unroll
            for (int p = 0; p < 8; p++) ffma2(acc[p], a, wp[p]);
        }
    }

    float o[16];
#pragma unroll
    for (int p = 0; p < 8; p++) unpack2(acc[p], o[2 * p], o[2 * p + 1]);

    float* op = g_hp2 + (size_t)n * D2;
    *(float4*)(op + 0)  = make_float4(o[0],  o[1],  o[2],  o[3]);
    *(float4*)(op + 4)  = make_float4(o[4],  o[5],  o[6],  o[7]);
    *(float4*)(op + 8)  = make_float4(o[8],  o[9],  o[10], o[11]);
    *(float4*)(op + 12) = make_float4(o[12], o[13], o[14], o[15]);

    float s = 0.f, d = 0.f;
#pragma unroll
    for (int c = 0; c < D2; c++) {
        s = fmaf(o[c], A2[c], s);
        d = fmaf(o[c], A2[D2 + c], d);
    }
    g_al2s[n] = s;
    g_al2d[n] = d;
}

// ---------------- layer-2 aggregation + bias + log_softmax ----------------
__global__ __launch_bounds__(256) void kagg2(const float* __restrict__ b2,
                                             float* __restrict__ out) {
    int gw = (blockIdx.x * blockDim.x + threadIdx.x) >> 5;
    if (gw >= NV) return;
    const int d    = gw;
    const int lane = threadIdx.x & 31;
    const int half = lane >> 4;
    const int hl   = lane & 15;

    float al2dd = g_al2d[d];
    float acc = 0.f, den = 0.f;

    if (half == 0) {
        float v = g_al2s[d] + al2dd;
        v = (v > 0.f) ? v : 0.2f * v;
        float w = __expf(v);
        den += w;
        acc = fmaf(g_hp2[(size_t)d * D2 + hl], w, acc);
    }

    const int beg = g_off[d], end = g_off[d + 1];
    for (int j = beg; j < end; j += 32) {
        int idx = j + lane;
        int sv  = g_esrc[(idx < end) ? idx : (end - 1)];
        int m   = end - j; if (m > 32) m = 32;
        for (int k = 0; k < m; k += 2) {
            int s0 = __shfl_sync(0xffffffffu, sv, k);
            int s1 = __shfl_sync(0xffffffffu, sv, (k + 1 < m) ? (k + 1) : k);
            int s  = (half == 0) ? s0 : s1;
            bool valid = (half == 0) || (k + 1 < m);
            if (valid) {
                float v = g_al2s[s] + al2dd;
                v = (v > 0.f) ? v : 0.2f * v;
                float w = __expf(v);
                den += w;
                acc = fmaf(g_hp2[(size_t)s * D2 + hl], w, acc);
            }
        }
    }
    acc += __shfl_xor_sync(0xffffffffu, acc, 16);
    den += __shfl_xor_sync(0xffffffffu, den, 16);

    float v = acc / den + b2[hl];
    float mx = v;
#pragma unroll
    for (int off = 8; off >= 1; off >>= 1)
        mx = fmaxf(mx, __shfl_xor_sync(0xffffffffu, mx, off));
    float se = __expf(v - mx);
#pragma unroll
    for (int off = 8; off >= 1; off >>= 1)
        se += __shfl_xor_sync(0xffffffffu, se, off);
    float r = v - (mx + logf(se));
    if (lane < 16) out[(size_t)d * D2 + hl] = r;
}

// ---------------- launch ----------------
extern "C" void kernel_launch(void* const* d_in, const int* in_sizes, int n_in,
                              void* d_out, int out_size) {
    const float* x   = (const float*)d_in[0];
    const int*   ei  = (const int*)d_in[1];
    const float* W1  = (const float*)d_in[2];
    const float* a1s = (const float*)d_in[3];
    const float* a1d = (const float*)d_in[4];
    const float* b1  = (const float*)d_in[5];
    const float* W2  = (const float*)d_in[6];
    const float* a2s = (const float*)d_in[7];
    const float* a2d = (const float*)d_in[8];
    const float* b2  = (const float*)d_in[9];
    float* out = (float*)d_out;

    const int* src = ei;
    const int* dst = ei + EE;

    kzero<<<(NV + 255) / 256, 256>>>();
    khist<<<(EE + 255) / 256, 256>>>(dst);
    kscan1<<<SCAN_NB, 256>>>();
    kscan2<<<1, 128>>>();
    kscan3<<<SCAN_NB, 256>>>();
    kfill<<<(EE + 255) / 256, 256>>>(src, dst);

    kgemm1<<<(NV + 127) / 128, 128>>>(x, W1, a1s, a1d);
    kagg1<<<(NV * 32 + 255) / 256, 256>>>(b1);
    kgemm2<<<(NV + 255) / 256, 256>>>(W2, a2s, a2d);
    kagg2<<<(NV * 32 + 255) / 256, 256>>>(b2, out);
}

// round 5
// speedup vs baseline: 2.4403x; 1.1197x over previous
#include <cuda_runtime.h>
#include <math.h>

#define NV  100000
#define EE  1600000
#define FIN 512
#define D1  64
#define H1N 8
#define D2  16
#define SCAN_CH 1024
#define SCAN_NB ((NV + SCAN_CH - 1) / SCAN_CH)   // 98

typedef unsigned long long u64;

// ---- packed f32x2 helpers (used by kgemm2) ----
__device__ __forceinline__ void ffma2(u64& d, u64 a, u64 b) {
    asm("fma.rn.f32x2 %0, %1, %2, %0;" : "+l"(d) : "l"(a), "l"(b));
}
__device__ __forceinline__ u64 pack2(float x, float y) {
    u64 r;
    asm("mov.b64 %0, {%1, %2};" : "=l"(r) : "f"(x), "f"(y));
    return r;
}
__device__ __forceinline__ void unpack2(u64 v, float& x, float& y) {
    asm("mov.b64 {%0, %1}, %2;" : "=f"(x), "=f"(y) : "l"(v));
}

// ---- tf32 helpers ----
__device__ __forceinline__ unsigned cvt_tf32(float x) {
    unsigned r;
    asm("cvt.rna.tf32.f32 %0, %1;" : "=r"(r) : "f"(x));
    return r;
}
__device__ __forceinline__ void mma_tf32(float* c, const unsigned* a, const unsigned* b) {
    asm volatile(
        "mma.sync.aligned.m16n8k8.row.col.f32.tf32.tf32.f32 "
        "{%0,%1,%2,%3}, {%4,%5,%6,%7}, {%8,%9}, {%0,%1,%2,%3};"
        : "+f"(c[0]), "+f"(c[1]), "+f"(c[2]), "+f"(c[3])
        : "r"(a[0]), "r"(a[1]), "r"(a[2]), "r"(a[3]), "r"(b[0]), "r"(b[1]));
}

// ---- scratch (device globals; no allocations allowed) ----
__device__ float g_hp1[(size_t)NV * D1];     // x @ W1            [N,64]
__device__ float g_al1s[NV * H1N];           // src logits        [N,8]
__device__ float g_al1d[NV * H1N];           // dst logits        [N,8]
__device__ float g_h1[(size_t)NV * D1];      // layer1 out (elu)  [N,64]
__device__ float g_hp2[(size_t)NV * D2];     // h1 @ W2           [N,16]
__device__ float g_al2s[NV];
__device__ float g_al2d[NV];
__device__ float g_Wsp[D1 * FIN * 2];        // W1 tf32 hi/lo, n-major [n][k][2]
__device__ int   g_cnt[NV];
__device__ int   g_cnt2[NV];
__device__ int   g_off[NV + 1];
__device__ int   g_esrc[EE];
__device__ int   g_blk[SCAN_NB];
__device__ int   g_blkoff[SCAN_NB];

// ---------------- zero CSR counters ----------------
__global__ void kzero() {
    int t = blockIdx.x * blockDim.x + threadIdx.x;
    if (t < NV) { g_cnt[t] = 0; g_cnt2[t] = 0; }
}

// ---------------- W1 tf32 hi/lo split (runs once per launch, tiny) -------
__global__ void ksplitW(const float* __restrict__ W1) {
    int t = blockIdx.x * blockDim.x + threadIdx.x;
    if (t >= FIN * D1) return;
    int k = t >> 6, n = t & 63;
    float w = W1[t];
    unsigned hi = cvt_tf32(w);
    float lo = w - __uint_as_float(hi);
    g_Wsp[(n * FIN + k) * 2 + 0] = __uint_as_float(hi);
    g_Wsp[(n * FIN + k) * 2 + 1] = __uint_as_float(cvt_tf32(lo));
}

// ---------------- CSR: histogram of dst ----------------
__global__ void khist(const int* __restrict__ dst) {
    int e = blockIdx.x * blockDim.x + threadIdx.x;
    if (e < EE) atomicAdd(&g_cnt[dst[e]], 1);
}

// ---------------- CSR: scan stage 1 (block sums) ----------------
__global__ __launch_bounds__(256) void kscan1() {
    __shared__ int wsum[8];
    int b = blockIdx.x, t = threadIdx.x;
    int base = b * SCAN_CH + t * 4;
    int s = 0;
#pragma unroll
    for (int l = 0; l < 4; l++) s += (base + l < NV) ? g_cnt[base + l] : 0;
#pragma unroll
    for (int off = 16; off >= 1; off >>= 1) s += __shfl_down_sync(0xffffffffu, s, off);
    if ((t & 31) == 0) wsum[t >> 5] = s;
    __syncthreads();
    if (t == 0) {
        int tot = 0;
#pragma unroll
        for (int w = 0; w < 8; w++) tot += wsum[w];
        g_blk[b] = tot;
    }
}

// ---------------- CSR: scan stage 2 ----------------
__global__ __launch_bounds__(128) void kscan2() {
    __shared__ int sm[128];
    int t = threadIdx.x;
    int v = (t < SCAN_NB) ? g_blk[t] : 0;
    sm[t] = v;
    __syncthreads();
    for (int off = 1; off < 128; off <<= 1) {
        int y = (t >= off) ? sm[t - off] : 0;
        __syncthreads();
        sm[t] += y;
        __syncthreads();
    }
    if (t < SCAN_NB) g_blkoff[t] = sm[t] - v;   // exclusive
}

// ---------------- CSR: scan stage 3 ----------------
__global__ __launch_bounds__(256) void kscan3() {
    __shared__ int wsum[8];
    int b = blockIdx.x, t = threadIdx.x;
    int lane = t & 31, w = t >> 5;
    int base = b * SCAN_CH + t * 4;
    int v[4];
#pragma unroll
    for (int l = 0; l < 4; l++) v[l] = (base + l < NV) ? g_cnt[base + l] : 0;
    int s4 = v[0] + v[1] + v[2] + v[3];
    int x = s4;
#pragma unroll
    for (int off = 1; off < 32; off <<= 1) {
        int y = __shfl_up_sync(0xffffffffu, x, off);
        if (lane >= off) x += y;
    }
    if (lane == 31) wsum[w] = x;
    __syncthreads();
    if (t < 8) {
        int y = wsum[t];
#pragma unroll
        for (int off = 1; off < 8; off <<= 1) {
            int z = __shfl_up_sync(0x000000ffu, y, off);
            if (t >= off) y += z;
        }
        wsum[t] = y;
    }
    __syncthreads();
    int run = g_blkoff[b] + (x - s4) + (w > 0 ? wsum[w - 1] : 0);
#pragma unroll
    for (int l = 0; l < 4; l++) {
        if (base + l < NV) g_off[base + l] = run;
        run += v[l];
    }
    if (b == 0 && t == 0) g_off[NV] = EE;
}

// ---------------- CSR: fill ----------------
__global__ void kfill(const int* __restrict__ src, const int* __restrict__ dst) {
    int e = blockIdx.x * blockDim.x + threadIdx.x;
    if (e >= EE) return;
    int d = dst[e];
    int p = g_off[d] + atomicAdd(&g_cnt2[d], 1);
    g_esrc[p] = src[e];
}

// ---------------- GEMM1: hp1 = x @ W1 via 3xTF32 tensor MMA -----------------
// 128x64 block tile, 256 threads (8 warps of 32x32), fused al1 epilogue.
__global__ __launch_bounds__(256) void kgemm1(const float* __restrict__ x,
                                              const float* __restrict__ a1s,
                                              const float* __restrict__ a1d) {
    __shared__ float As[128][36];     // raw fp32 A tile (pad 36: conflict-free)
    __shared__ float Bst[64][68];     // W tile, [n][2k]=(hi,lo), pad 68

    const int tid   = threadIdx.x;
    const int lane  = tid & 31;
    const int wid   = tid >> 5;
    const int g     = lane >> 2;      // groupID 0..7
    const int tg    = lane & 3;       // thread-in-group 0..3
    const int warpM = wid & 3;        // 4 warps along M
    const int warpN = wid >> 2;       // 2 warps along N
    const int row0  = blockIdx.x * 128;

    float acc[2][4][4];
#pragma unroll
    for (int mi = 0; mi < 2; mi++)
#pragma unroll
        for (int ni = 0; ni < 4; ni++)
#pragma unroll
            for (int q = 0; q < 4; q++) acc[mi][ni][q] = 0.f;

    float4 rx[4], rb[4];
    const float4 z4 = make_float4(0.f, 0.f, 0.f, 0.f);
    // prefetch kk = 0
#pragma unroll
    for (int l = 0; l < 4; l++) {
        int f = l * 256 + tid, r = f >> 3, c4 = (f & 7) * 4, row = row0 + r;
        rx[l] = (row < NV) ? *(const float4*)(x + (size_t)row * FIN + c4) : z4;
    }
#pragma unroll
    for (int l = 0; l < 4; l++) {
        int f = l * 256 + tid, n = f >> 4, c = (f & 15) * 4;
        rb[l] = *(const float4*)(g_Wsp + n * (FIN * 2) + c);
    }

    for (int kk = 0; kk < FIN; kk += 32) {
#pragma unroll
        for (int l = 0; l < 4; l++) {
            int f = l * 256 + tid, r = f >> 3, c4 = (f & 7) * 4;
            *(float4*)&As[r][c4] = rx[l];
        }
#pragma unroll
        for (int l = 0; l < 4; l++) {
            int f = l * 256 + tid, n = f >> 4, c = (f & 15) * 4;
            *(float4*)&Bst[n][c] = rb[l];
        }
        __syncthreads();

        if (kk + 32 < FIN) {
            int kn = kk + 32;
#pragma unroll
            for (int l = 0; l < 4; l++) {
                int f = l * 256 + tid, r = f >> 3, c4 = (f & 7) * 4, row = row0 + r;
                rx[l] = (row < NV) ? *(const float4*)(x + (size_t)row * FIN + kn + c4) : z4;
            }
#pragma unroll
            for (int l = 0; l < 4; l++) {
                int f = l * 256 + tid, n = f >> 4, c = (f & 15) * 4;
                rb[l] = *(const float4*)(g_Wsp + n * (FIN * 2) + kn * 2 + c);
            }
        }

#pragma unroll
        for (int k8 = 0; k8 < 4; k8++) {
            // A fragments (on-the-fly tf32 hi/lo split)
            unsigned a_hi[2][4], a_lo[2][4];
#pragma unroll
            for (int mi = 0; mi < 2; mi++) {
                int rbase = warpM * 32 + mi * 16 + g;
#pragma unroll
                for (int q = 0; q < 4; q++) {
                    int rr = rbase + (q & 1) * 8;
                    int ck = k8 * 8 + tg + (q >> 1) * 4;
                    float v = As[rr][ck];
                    unsigned hi = cvt_tf32(v);
                    a_hi[mi][q] = hi;
                    a_lo[mi][q] = cvt_tf32(v - __uint_as_float(hi));
                }
            }
            // B fragments (pre-split hi/lo pairs)
            unsigned b_hi[4][2], b_lo[4][2];
#pragma unroll
            for (int ni = 0; ni < 4; ni++) {
                int n = warpN * 32 + ni * 8 + g;
#pragma unroll
                for (int q = 0; q < 2; q++) {
                    int ck = k8 * 8 + tg + q * 4;
                    float2 hl = *(const float2*)&Bst[n][2 * ck];
                    b_hi[ni][q] = __float_as_uint(hl.x);
                    b_lo[ni][q] = __float_as_uint(hl.y);
                }
            }
            // 3xTF32: lo terms first, hi.hi last
#pragma unroll
            for (int mi = 0; mi < 2; mi++)
#pragma unroll
                for (int ni = 0; ni < 4; ni++) {
                    mma_tf32(acc[mi][ni], a_lo[mi], b_hi[ni]);
                    mma_tf32(acc[mi][ni], a_hi[mi], b_lo[ni]);
                    mma_tf32(acc[mi][ni], a_hi[mi], b_hi[ni]);
                }
        }
        __syncthreads();
    }

    // epilogue: store hp1 + fused attention projections
    float2 as2[4], ad2[4];
#pragma unroll
    for (int ni = 0; ni < 4; ni++) {
        int h = warpN * 4 + ni;
        as2[ni] = make_float2(a1s[h * 8 + 2 * tg], a1s[h * 8 + 2 * tg + 1]);
        ad2[ni] = make_float2(a1d[h * 8 + 2 * tg], a1d[h * 8 + 2 * tg + 1]);
    }
#pragma unroll
    for (int mi = 0; mi < 2; mi++)
#pragma unroll
        for (int rh = 0; rh < 2; rh++) {
            int row = row0 + warpM * 32 + mi * 16 + rh * 8 + g;
            bool ok = row < NV;
#pragma unroll
            for (int ni = 0; ni < 4; ni++) {
                float c0 = acc[mi][ni][rh * 2], c1 = acc[mi][ni][rh * 2 + 1];
                if (ok) {
                    int col = warpN * 32 + ni * 8 + 2 * tg;
                    *(float2*)(g_hp1 + (size_t)row * D1 + col) = make_float2(c0, c1);
                }
                float sp = c0 * as2[ni].x + c1 * as2[ni].y;
                float dp = c0 * ad2[ni].x + c1 * ad2[ni].y;
                sp += __shfl_xor_sync(0xffffffffu, sp, 1);
                sp += __shfl_xor_sync(0xffffffffu, sp, 2);
                dp += __shfl_xor_sync(0xffffffffu, dp, 1);
                dp += __shfl_xor_sync(0xffffffffu, dp, 2);
                if (ok && tg == ni) {
                    g_al1s[row * H1N + warpN * 4 + ni] = sp;
                    g_al1d[row * H1N + warpN * 4 + ni] = dp;
                }
            }
        }
}

// ---------------- layer-1 aggregation: warp/dst, float2 channel pairs --------
__global__ __launch_bounds__(256) void kagg1(const float* __restrict__ b1) {
    int gw = (blockIdx.x * blockDim.x + threadIdx.x) >> 5;
    if (gw >= NV) return;
    const int d    = gw;
    const int lane = threadIdx.x & 31;
    const int hsel = lane >> 2;            // head of channels (2l, 2l+1)

    float ald = (lane < 8) ? g_al1d[d * H1N + lane] : 0.f;
    float accx = 0.f, accy = 0.f, den = 0.f;

    // self-loop
    {
        int s = d;
        float w = 0.f;
        if (lane < 8) {
            float v = g_al1s[s * H1N + lane] + ald;
            v = (v > 0.f) ? v : 0.2f * v;
            w = __expf(v);
            den += w;
        }
        float wl = __shfl_sync(0xffffffffu, w, hsel);
        float2 hv = *(const float2*)&g_hp1[(size_t)s * D1 + 2 * lane];
        accx = fmaf(hv.x, wl, accx);
        accy = fmaf(hv.y, wl, accy);
    }

    const int beg = g_off[d], end = g_off[d + 1];
    for (int j = beg; j < end; j += 32) {
        int idx = j + lane;
        int sv  = g_esrc[(idx < end) ? idx : (end - 1)];
        int m   = end - j; if (m > 32) m = 32;
        for (int k = 0; k < m; k++) {
            int s = __shfl_sync(0xffffffffu, sv, k);
            float w = 0.f;
            if (lane < 8) {
                float v = g_al1s[s * H1N + lane] + ald;
                v = (v > 0.f) ? v : 0.2f * v;
                w = __expf(v);
                den += w;
            }
            float wl = __shfl_sync(0xffffffffu, w, hsel);
            float2 hv = *(const float2*)&g_hp1[(size_t)s * D1 + 2 * lane];
            accx = fmaf(hv.x, wl, accx);
            accy = fmaf(hv.y, wl, accy);
        }
    }

    float dl = __shfl_sync(0xffffffffu, den, hsel);
    float v0 = accx / dl + b1[2 * lane];
    float v1 = accy / dl + b1[2 * lane + 1];
    v0 = (v0 > 0.f) ? v0 : expm1f(v0);   // ELU
    v1 = (v1 > 0.f) ? v1 : expm1f(v1);
    *(float2*)&g_h1[(size_t)d * D1 + 2 * lane] = make_float2(v0, v1);
}

// ---------------- GEMM2 (f32x2, one thread/node) + fused al2 ----------------
__global__ __launch_bounds__(256) void kgemm2(const float* __restrict__ W2,
                                              const float* __restrict__ a2s,
                                              const float* __restrict__ a2d) {
    __shared__ float Ws[D1 * D2];
    __shared__ float A2[2 * D2];
    int tid = threadIdx.x;
    for (int i = tid; i < D1 * D2; i += 256) Ws[i] = W2[i];
    if (tid < D2)           A2[tid] = a2s[tid];
    else if (tid < 2 * D2)  A2[tid] = a2d[tid - D2];
    __syncthreads();

    int n = blockIdx.x * 256 + tid;
    if (n >= NV) return;

    u64 acc[8];
#pragma unroll
    for (int p = 0; p < 8; p++) acc[p] = 0ULL;

    const float* hr = g_h1 + (size_t)n * D1;
#pragma unroll
    for (int k0 = 0; k0 < D1; k0 += 4) {
        float4 hv = *(const float4*)(hr + k0);
        float h4[4] = {hv.x, hv.y, hv.z, hv.w};
#pragma unroll
        for (int j = 0; j < 4; j++) {
            u64 a = pack2(h4[j], h4[j]);
            const u64* wp = (const u64*)&Ws[(k0 + j) * D2];
#pragma unroll
            for (int p = 0; p < 8; p++) ffma2(acc[p], a, wp[p]);
        }
    }

    float o[16];
#pragma unroll
    for (int p = 0; p < 8; p++) unpack2(acc[p], o[2 * p], o[2 * p + 1]);

    float* op = g_hp2 + (size_t)n * D2;
    *(float4*)(op + 0)  = make_float4(o[0],  o[1],  o[2],  o[3]);
    *(float4*)(op + 4)  = make_float4(o[4],  o[5],  o[6],  o[7]);
    *(float4*)(op + 8)  = make_float4(o[8],  o[9],  o[10], o[11]);
    *(float4*)(op + 12) = make_float4(o[12], o[13], o[14], o[15]);

    float s = 0.f, d = 0.f;
#pragma unroll
    for (int c = 0; c < D2; c++) {
        s = fmaf(o[c], A2[c], s);
        d = fmaf(o[c], A2[D2 + c], d);
    }
    g_al2s[n] = s;
    g_al2d[n] = d;
}

// ---------------- layer-2 aggregation + bias + log_softmax ----------------
// Warp/dst: 4 octets of 8 lanes each process 4 edges/iteration; channel pair
// per lane; all shfls warp-uniform.
__global__ __launch_bounds__(256) void kagg2(const float* __restrict__ b2,
                                             float* __restrict__ out) {
    int gw = (blockIdx.x * blockDim.x + threadIdx.x) >> 5;
    if (gw >= NV) return;
    const int d    = gw;
    const int lane = threadIdx.x & 31;
    const int oct  = lane >> 3;
    const int ol   = lane & 7;

    float al2dd = g_al2d[d];
    float accx = 0.f, accy = 0.f, den = 0.f;

    // self-loop handled by oct 0 (no shfl inside)
    if (oct == 0) {
        float v = g_al2s[d] + al2dd;
        v = (v > 0.f) ? v : 0.2f * v;
        float w = __expf(v);
        den += w;
        float2 hv = *(const float2*)&g_hp2[(size_t)d * D2 + 2 * ol];
        accx = fmaf(hv.x, w, accx);
        accy = fmaf(hv.y, w, accy);
    }

    const int beg = g_off[d], end = g_off[d + 1];
    for (int j = beg; j < end; j += 32) {
        int idx = j + lane;
        int sv  = g_esrc[(idx < end) ? idx : (end - 1)];
        int m   = end - j; if (m > 32) m = 32;
        for (int k = 0; k < m; k += 4) {
            int s0 = __shfl_sync(0xffffffffu, sv, k);
            int s1 = __shfl_sync(0xffffffffu, sv, (k + 1 < m) ? (k + 1) : k);
            int s2 = __shfl_sync(0xffffffffu, sv, (k + 2 < m) ? (k + 2) : k);
            int s3 = __shfl_sync(0xffffffffu, sv, (k + 3 < m) ? (k + 3) : k);
            int s  = (oct == 0) ? s0 : (oct == 1) ? s1 : (oct == 2) ? s2 : s3;
            bool valid = (k + oct) < m;
            if (valid) {
                float v = g_al2s[s] + al2dd;
                v = (v > 0.f) ? v : 0.2f * v;
                float w = __expf(v);
                den += w;
                float2 hv = *(const float2*)&g_hp2[(size_t)s * D2 + 2 * ol];
                accx = fmaf(hv.x, w, accx);
                accy = fmaf(hv.y, w, accy);
            }
        }
    }
    // reduce across octets (each lane keeps its channel pair)
    accx += __shfl_xor_sync(0xffffffffu, accx, 8);
    accx += __shfl_xor_sync(0xffffffffu, accx, 16);
    accy += __shfl_xor_sync(0xffffffffu, accy, 8);
    accy += __shfl_xor_sync(0xffffffffu, accy, 16);
    den  += __shfl_xor_sync(0xffffffffu, den, 8);
    den  += __shfl_xor_sync(0xffffffffu, den, 16);

    float v0 = accx / den + b2[2 * ol];
    float v1 = accy / den + b2[2 * ol + 1];
    // log_softmax over 16 channels (pairs on 8 lanes, replicated across octs)
    float mx = fmaxf(v0, v1);
#pragma unroll
    for (int off = 4; off >= 1; off >>= 1)
        mx = fmaxf(mx, __shfl_xor_sync(0xffffffffu, mx, off));
    float se = __expf(v0 - mx) + __expf(v1 - mx);
#pragma unroll
    for (int off = 4; off >= 1; off >>= 1)
        se += __shfl_xor_sync(0xffffffffu, se, off);
    float lse = mx + logf(se);
    if (lane < 8)
        *(float2*)&out[(size_t)d * D2 + 2 * ol] = make_float2(v0 - lse, v1 - lse);
}

// ---------------- launch ----------------
extern "C" void kernel_launch(void* const* d_in, const int* in_sizes, int n_in,
                              void* d_out, int out_size) {
    const float* x   = (const float*)d_in[0];
    const int*   ei  = (const int*)d_in[1];
    const float* W1  = (const float*)d_in[2];
    const float* a1s = (const float*)d_in[3];
    const float* a1d = (const float*)d_in[4];
    const float* b1  = (const float*)d_in[5];
    const float* W2  = (const float*)d_in[6];
    const float* a2s = (const float*)d_in[7];
    const float* a2d = (const float*)d_in[8];
    const float* b2  = (const float*)d_in[9];
    float* out = (float*)d_out;

    const int* src = ei;
    const int* dst = ei + EE;

    kzero<<<(NV + 255) / 256, 256>>>();
    ksplitW<<<(FIN * D1 + 255) / 256, 256>>>(W1);
    khist<<<(EE + 255) / 256, 256>>>(dst);
    kscan1<<<SCAN_NB, 256>>>();
    kscan2<<<1, 128>>>();
    kscan3<<<SCAN_NB, 256>>>();
    kfill<<<(EE + 255) / 256, 256>>>(src, dst);

    kgemm1<<<(NV + 127) / 128, 256>>>(x, a1s, a1d);
    kagg1<<<(NV * 32 + 255) / 256, 256>>>(b1);
    kgemm2<<<(NV + 255) / 256, 256>>>(W2, a2s, a2d);
    kagg2<<<(NV * 32 + 255) / 256, 256>>>(b2, out);
}